// round 5
// baseline (speedup 1.0000x reference)
#include <cuda_runtime.h>
#include <cuda_fp16.h>
#include <math.h>

#define B_  256
#define T_  512
#define S_  64
#define O_  128
#define H_  128
#define G4  512   // 4*H
#define BT_ ((size_t)B_ * T_)

// ---------------- scratch (device globals; no runtime allocation) ----------
__device__ __half g_gzh[BT_ * G4];         // 134 MB : obs@K + b (half)
__device__ __half g_hsh[BT_ * H_];         // 33.5 MB LSTM hidden (half)
__device__ __half g_pmh[BT_ * S_];         // 16.8 MB posterior mean (half)
__device__ float  g_ps [BT_ * S_];         // 33.5 MB posterior scale (fp32)
__device__ __half g_KTh [512 * 128];       // K^T  (n-major)
__device__ __half g_RTh [512 * 128];       // R^T  (n-major)  <-- for tensor lstm
__device__ __half g_WrTh[128 * 128];       // [Wrm|Wrs]^T (n-major, n<64 mean)
__device__ __half g_WgTh[256 * 64];        // [Wgm|Wgs]^T (n-major, n<128 mean)
__device__ double g_acc[2];                // [0]=KL sum, [1]=recon-logp sum

__device__ __forceinline__ float softplusf_(float x) {
    return fmaxf(x, 0.f) + __logf(1.f + __expf(-fabsf(x)));
}
__device__ __forceinline__ float tanha_(float x) {
    float y; asm("tanh.approx.f32 %0, %1;" : "=f"(y) : "f"(x)); return y;
}
__device__ __forceinline__ float sigt_(float x) {   // sigmoid via MUFU.TANH
    return fmaf(tanha_(0.5f * x), 0.5f, 0.5f);
}

__device__ __forceinline__ void mma16816(float* c, const unsigned* a, const unsigned* b) {
    asm volatile(
        "mma.sync.aligned.m16n8k16.row.col.f32.f16.f16.f32 "
        "{%0,%1,%2,%3}, {%4,%5,%6,%7}, {%8,%9}, {%0,%1,%2,%3};\n"
        : "+f"(c[0]), "+f"(c[1]), "+f"(c[2]), "+f"(c[3])
        : "r"(a[0]), "r"(a[1]), "r"(a[2]), "r"(a[3]), "r"(b[0]), "r"(b[1]));
}
__device__ __forceinline__ void ldsm4(unsigned* a, unsigned addr) {
    asm volatile("ldmatrix.sync.aligned.m8n8.x4.shared.b16 {%0,%1,%2,%3}, [%4];\n"
                 : "=r"(a[0]), "=r"(a[1]), "=r"(a[2]), "=r"(a[3]) : "r"(addr));
}

// ---------------------------------------------------------------------------
__global__ void k_zero() { if (threadIdx.x < 2) g_acc[threadIdx.x] = 0.0; }

// weight transposes/concats -> half
__global__ void k_prep_w(const float* __restrict__ K,  const float* __restrict__ R,
                         const float* __restrict__ Wrm, const float* __restrict__ Wrs,
                         const float* __restrict__ Wgm, const float* __restrict__ Wgs) {
    int stride = gridDim.x * blockDim.x;
    for (int i = blockIdx.x * blockDim.x + threadIdx.x; i < 163840; i += stride) {
        if (i < 65536) {
            int n = i >> 7, k = i & 127;
            g_KTh[i] = __float2half(K[k * 512 + n]);
        } else if (i < 81920) {
            int j = i - 65536; int n = j >> 7, k = j & 127;
            float v = (n < 64) ? Wrm[k * 64 + n] : Wrs[k * 64 + (n - 64)];
            g_WrTh[j] = __float2half(v);
        } else if (i < 98304) {
            int j = i - 81920; int n = j >> 6, k = j & 63;
            float v = (n < 128) ? Wgm[k * 128 + n] : Wgs[k * 128 + (n - 128)];
            g_WgTh[j] = __float2half(v);
        } else {
            int j = i - 98304; int n = j >> 7, k = j & 127;
            g_RTh[j] = __float2half(R[k * 512 + n]);
        }
    }
}

// ---------------------------------------------------------------------------
// gz = obs @ K + b via HMMA, output half, smem-staged coalesced stores.
__global__ __launch_bounds__(256) void k_xk(const float* __restrict__ obs,
                                            const float* __restrict__ bl) {
    extern __shared__ __half sm[];
    __half* As = sm;                 // [128][136]
    __half* Bt = sm + 128 * 136;     // [128][136]  (K^T tile / later C staging)
    const int tid = threadIdx.x;
    const int bt0 = blockIdx.y * 128;
    const int c0  = blockIdx.x * 128;

    const float4* ap = (const float4*)(obs + (size_t)bt0 * 128);
    #pragma unroll
    for (int i = tid; i < 128 * 32; i += 256) {
        int r = i >> 5, c = i & 31;
        float4 v = ap[r * 32 + c];
        *(half2*)&As[r * 136 + c * 4]     = __floats2half2_rn(v.x, v.y);
        *(half2*)&As[r * 136 + c * 4 + 2] = __floats2half2_rn(v.z, v.w);
    }
    const uint4* bp = (const uint4*)(g_KTh + (size_t)c0 * 128);
    #pragma unroll
    for (int i = tid; i < 128 * 16; i += 256) {
        int r = i >> 4, c = i & 15;
        *(uint4*)&Bt[r * 136 + c * 8] = bp[r * 16 + c];
    }
    __syncthreads();

    const int w = tid >> 5, l = tid & 31, g = l >> 2, tg = l & 3;
    const int m0 = w * 16;
    float acc[16][4];
    #pragma unroll
    for (int i = 0; i < 16; i++)
        #pragma unroll
        for (int j = 0; j < 4; j++) acc[i][j] = 0.f;

    #pragma unroll
    for (int kk = 0; kk < 8; kk++) {
        const int kb = kk * 16 + tg * 2;
        unsigned a[4];
        a[0] = *(const unsigned*)&As[(m0 + g)     * 136 + kb];
        a[1] = *(const unsigned*)&As[(m0 + g + 8) * 136 + kb];
        a[2] = *(const unsigned*)&As[(m0 + g)     * 136 + kb + 8];
        a[3] = *(const unsigned*)&As[(m0 + g + 8) * 136 + kb + 8];
        #pragma unroll
        for (int na = 0; na < 16; na++) {
            unsigned b[2];
            b[0] = *(const unsigned*)&Bt[(na * 8 + g) * 136 + kb];
            b[1] = *(const unsigned*)&Bt[(na * 8 + g) * 136 + kb + 8];
            mma16816(acc[na], a, b);
        }
    }
    __syncthreads();                 // done reading Bt; reuse it as C staging
    #pragma unroll
    for (int na = 0; na < 16; na++) {
        int cc = na * 8 + tg * 2;
        float2 bb = *(const float2*)&bl[c0 + cc];
        *(half2*)&Bt[(m0 + g) * 136 + cc]     = __floats2half2_rn(acc[na][0] + bb.x,
                                                                  acc[na][1] + bb.y);
        *(half2*)&Bt[(m0 + g + 8) * 136 + cc] = __floats2half2_rn(acc[na][2] + bb.x,
                                                                  acc[na][3] + bb.y);
    }
    __syncthreads();
    #pragma unroll
    for (int i = tid; i < 128 * 16; i += 256) {
        int r = i >> 4, c = i & 15;
        uint4 v = *(uint4*)&Bt[r * 136 + c * 8];
        *(uint4*)&g_gzh[(size_t)(bt0 + r) * 512 + c0 + c * 8] = v;
    }
}

// ---------------------------------------------------------------------------
// TENSOR-CORE LSTM: 16 blocks x 512 thr, 16 batch rows/block.
// Per step: z[16,512] = h[16,128] @ R^T via mma.m16n8k16, R^T frags persistent
// in registers (warp w owns n-cols [w*32, w*32+32)). gz prefetched 1 step.
__global__ __launch_bounds__(512, 1) void k_lstm() {
    __shared__ __half hA[16 * 136];     // h (A operand), padded ld=136
    __shared__ float  zb[16 * 520];     // z exchange, padded ld=520
    const int tid  = threadIdx.x;
    const int w    = tid >> 5, lane = tid & 31;
    const int g    = lane >> 2, tg = lane & 3;
    const int n0   = w * 32;
    const int b0   = blockIdx.x * 16;
    const int row  = tid >> 5;          // gate-stage batch row (0..15)

    // persistent B fragments: R^T[n0+nt*8+g][kt*16+tg*2 .. +1, +8..+9]
    unsigned wb[4][8][2];
    #pragma unroll
    for (int nt = 0; nt < 4; nt++)
        #pragma unroll
        for (int kt = 0; kt < 8; kt++) {
            const __half* rp = g_RTh + (size_t)(n0 + nt * 8 + g) * 128 + kt * 16 + tg * 2;
            wb[nt][kt][0] = *(const unsigned*)rp;
            wb[nt][kt][1] = *(const unsigned*)(rp + 8);
        }

    // zero h buffer
    for (int i = tid; i < 16 * 136 / 2; i += 512) ((unsigned*)hA)[i] = 0;
    float cst[4] = {0.f, 0.f, 0.f, 0.f};

    // gz prefetch for t=0 (half2 per (nt, row-half))
    unsigned gzc[8], gzn[8];
    #pragma unroll
    for (int nt = 0; nt < 4; nt++) {
        int col = n0 + nt * 8 + tg * 2;
        gzc[nt * 2]     = *(const unsigned*)&g_gzh[((size_t)(b0 + g) * T_) * 512 + col];
        gzc[nt * 2 + 1] = *(const unsigned*)&g_gzh[((size_t)(b0 + g + 8) * T_) * 512 + col];
    }
    unsigned hA_s = (unsigned)__cvta_generic_to_shared(hA);
    const unsigned lds_off =
        ((unsigned)(((lane & 7) + ((lane >> 3) & 1) * 8) * 136 + (lane >> 4) * 8)) * 2;
    __syncthreads();

    for (int t = 0; t < T_; t++) {
        if (t + 1 < T_) {
            #pragma unroll
            for (int nt = 0; nt < 4; nt++) {
                int col = n0 + nt * 8 + tg * 2;
                gzn[nt * 2]     = *(const unsigned*)
                    &g_gzh[((size_t)(b0 + g) * T_ + t + 1) * 512 + col];
                gzn[nt * 2 + 1] = *(const unsigned*)
                    &g_gzh[((size_t)(b0 + g + 8) * T_ + t + 1) * 512 + col];
            }
        }
        float zc[4][4];
        #pragma unroll
        for (int nt = 0; nt < 4; nt++)
            #pragma unroll
            for (int j = 0; j < 4; j++) zc[nt][j] = 0.f;

        #pragma unroll
        for (int kt = 0; kt < 8; kt++) {
            unsigned a[4];
            ldsm4(a, hA_s + lds_off + kt * 32);   // +kt*16 halves
            #pragma unroll
            for (int nt = 0; nt < 4; nt++) mma16816(zc[nt], a, wb[nt][kt]);
        }
        #pragma unroll
        for (int nt = 0; nt < 4; nt++) {
            int col = n0 + nt * 8 + tg * 2;
            float2 lo = __half22float2(*(half2*)&gzc[nt * 2]);
            float2 hi = __half22float2(*(half2*)&gzc[nt * 2 + 1]);
            *(float2*)&zb[g * 520 + col]       = make_float2(zc[nt][0] + lo.x,
                                                             zc[nt][1] + lo.y);
            *(float2*)&zb[(g + 8) * 520 + col] = make_float2(zc[nt][2] + hi.x,
                                                             zc[nt][3] + hi.y);
        }
        __syncthreads();
        #pragma unroll
        for (int j = 0; j < 4; j++) {
            int u = lane + 32 * j;
            float zi = zb[row * 520 + u];
            float zf = zb[row * 520 + 128 + u];
            float zg = zb[row * 520 + 256 + u];
            float zo = zb[row * 520 + 384 + u];
            cst[j] = sigt_(zf) * cst[j] + sigt_(zi) * tanha_(zg);
            float hv = sigt_(zo) * tanha_(cst[j]);
            hA[row * 136 + u] = __float2half(hv);
        }
        __syncthreads();
        // flush h to gmem (concurrent with next step's reads of hA)
        {
            int ck = lane;
            uint2 v = *(uint2*)&hA[row * 136 + ck * 4];
            *(uint2*)&g_hsh[((size_t)(b0 + row) * T_ + t) * 128 + ck * 4] = v;
        }
        #pragma unroll
        for (int i = 0; i < 8; i++) gzc[i] = gzn[i];
    }
}

// ---------------------------------------------------------------------------
// heads: [hs]@[Wrm|Wrs] via HMMA.  grid 1024, 256 thr.  tile 128x128, k=128.
__global__ __launch_bounds__(256) void k_heads(const float* __restrict__ brm,
                                               const float* __restrict__ brs) {
    extern __shared__ __half sm[];
    __half* As = sm;                 // [128][136]
    __half* Bt = sm + 128 * 136;     // [128][136]
    const int tid = threadIdx.x;
    const int bt0 = blockIdx.x * 128;

    const uint4* ap = (const uint4*)(g_hsh + (size_t)bt0 * 128);
    const uint4* bp = (const uint4*)g_WrTh;
    #pragma unroll
    for (int i = tid; i < 128 * 16; i += 256) {
        int r = i >> 4, c = i & 15;
        *(uint4*)&As[r * 136 + c * 8] = ap[r * 16 + c];
        *(uint4*)&Bt[r * 136 + c * 8] = bp[r * 16 + c];
    }
    __syncthreads();

    const int w = tid >> 5, l = tid & 31, g = l >> 2, tg = l & 3;
    const int m0 = w * 16;
    float acc[16][4];
    #pragma unroll
    for (int i = 0; i < 16; i++)
        #pragma unroll
        for (int j = 0; j < 4; j++) acc[i][j] = 0.f;

    #pragma unroll
    for (int kk = 0; kk < 8; kk++) {
        const int kb = kk * 16 + tg * 2;
        unsigned a[4];
        a[0] = *(const unsigned*)&As[(m0 + g)     * 136 + kb];
        a[1] = *(const unsigned*)&As[(m0 + g + 8) * 136 + kb];
        a[2] = *(const unsigned*)&As[(m0 + g)     * 136 + kb + 8];
        a[3] = *(const unsigned*)&As[(m0 + g + 8) * 136 + kb + 8];
        #pragma unroll
        for (int na = 0; na < 16; na++) {
            unsigned b[2];
            b[0] = *(const unsigned*)&Bt[(na * 8 + g) * 136 + kb];
            b[1] = *(const unsigned*)&Bt[(na * 8 + g) * 136 + kb + 8];
            mma16816(acc[na], a, b);
        }
    }
    #pragma unroll
    for (int na = 0; na < 16; na++) {
        int cc = na * 8 + tg * 2;                 // 0..127 within concat
        int r0 = bt0 + m0 + g, r1 = r0 + 8;
        if (cc < 64) {
            float2 bm = *(const float2*)&brm[cc];
            *(half2*)&g_pmh[(size_t)r0 * 64 + cc] =
                __floats2half2_rn(acc[na][0] + bm.x, acc[na][1] + bm.y);
            *(half2*)&g_pmh[(size_t)r1 * 64 + cc] =
                __floats2half2_rn(acc[na][2] + bm.x, acc[na][3] + bm.y);
        } else {
            int c2 = cc - 64;
            float2 bs = *(const float2*)&brs[c2];
            *(float2*)&g_ps[(size_t)r0 * 64 + c2] =
                make_float2(softplusf_(acc[na][0] + bs.x), softplusf_(acc[na][1] + bs.y));
            *(float2*)&g_ps[(size_t)r1 * 64 + c2] =
                make_float2(softplusf_(acc[na][2] + bs.x), softplusf_(acc[na][3] + bs.y));
        }
    }
}

// ---------------------------------------------------------------------------
// generator + recon term via HMMA, fused reduction.  grid 1024, 512 thr.
__global__ __launch_bounds__(512) void k_gen(const float* __restrict__ obs,
                                             const float* __restrict__ bgm,
                                             const float* __restrict__ bgs) {
    extern __shared__ __half sm[];
    __half* As = sm;                 // [128][72]
    __half* Bt = sm + 128 * 72;      // [256][72]
    __shared__ float red[16];
    const int tid = threadIdx.x;
    const int bt0 = blockIdx.x * 128;

    const uint4* ap = (const uint4*)(g_pmh + (size_t)bt0 * 64);
    #pragma unroll
    for (int i = tid; i < 128 * 8; i += 512) {
        int r = i >> 3, c = i & 7;
        *(uint4*)&As[r * 72 + c * 8] = ap[r * 8 + c];
    }
    const uint4* bp = (const uint4*)g_WgTh;
    #pragma unroll
    for (int i = tid; i < 256 * 8; i += 512) {
        int r = i >> 3, c = i & 7;
        *(uint4*)&Bt[r * 72 + c * 8] = bp[i];
    }
    __syncthreads();

    const int w = tid >> 5, l = tid & 31, g = l >> 2, tg = l & 3;
    const int strip = w >> 1, ch = w & 1;
    const int m0 = strip * 16;
    float am[8][4], as_[8][4];
    #pragma unroll
    for (int i = 0; i < 8; i++)
        #pragma unroll
        for (int j = 0; j < 4; j++) { am[i][j] = 0.f; as_[i][j] = 0.f; }

    #pragma unroll
    for (int kk = 0; kk < 4; kk++) {
        const int kb = kk * 16 + tg * 2;
        unsigned a[4];
        a[0] = *(const unsigned*)&As[(m0 + g)     * 72 + kb];
        a[1] = *(const unsigned*)&As[(m0 + g + 8) * 72 + kb];
        a[2] = *(const unsigned*)&As[(m0 + g)     * 72 + kb + 8];
        a[3] = *(const unsigned*)&As[(m0 + g + 8) * 72 + kb + 8];
        #pragma unroll
        for (int na = 0; na < 8; na++) {
            int nmu = ch * 64 + na * 8 + g;
            unsigned b[2], b2[2];
            b[0]  = *(const unsigned*)&Bt[nmu * 72 + kb];
            b[1]  = *(const unsigned*)&Bt[nmu * 72 + kb + 8];
            b2[0] = *(const unsigned*)&Bt[(nmu + 128) * 72 + kb];
            b2[1] = *(const unsigned*)&Bt[(nmu + 128) * 72 + kb + 8];
            mma16816(am[na], a, b);
            mma16816(as_[na], a, b2);
        }
    }

    float lsum = 0.f;
    #pragma unroll
    for (int na = 0; na < 8; na++) {
        int oc = ch * 64 + na * 8 + tg * 2;
        float2 bm2 = *(const float2*)&bgm[oc];
        float2 bs2 = *(const float2*)&bgs[oc];
        int r0 = bt0 + m0 + g, r1 = r0 + 8;
        float2 o0 = *(const float2*)&obs[(size_t)r0 * 128 + oc];
        float2 o1 = *(const float2*)&obs[(size_t)r1 * 128 + oc];
        float mu, sg, d;
        mu = am[na][0] + bm2.x; sg = softplusf_(as_[na][0] + bs2.x);
        d = __fdividef(o0.x - mu, sg); lsum += -0.5f * d * d - __logf(sg);
        mu = am[na][1] + bm2.y; sg = softplusf_(as_[na][1] + bs2.y);
        d = __fdividef(o0.y - mu, sg); lsum += -0.5f * d * d - __logf(sg);
        mu = am[na][2] + bm2.x; sg = softplusf_(as_[na][2] + bs2.x);
        d = __fdividef(o1.x - mu, sg); lsum += -0.5f * d * d - __logf(sg);
        mu = am[na][3] + bm2.y; sg = softplusf_(as_[na][3] + bs2.y);
        d = __fdividef(o1.y - mu, sg); lsum += -0.5f * d * d - __logf(sg);
    }
    lsum -= 32.f * 0.91893853320467274f;   // 32 elements x 0.5*log(2pi)

    #pragma unroll
    for (int off = 16; off; off >>= 1) lsum += __shfl_down_sync(0xffffffffu, lsum, off);
    if (l == 0) red[w] = lsum;
    __syncthreads();
    if (tid == 0) {
        float s = 0.f;
        #pragma unroll
        for (int i = 0; i < 16; i++) s += red[i];
        atomicAdd(&g_acc[1], (double)s);
    }
}

// ---------------------------------------------------------------------------
// Prior rollout + KL. 256 blocks x 64 thr. Weights in half2 registers. (R3 ver)
__global__ __launch_bounds__(64) void k_prior(const float* __restrict__ im,
                                              const float* __restrict__ Wfm,
                                              const float* __restrict__ bfm,
                                              const float* __restrict__ Wfs,
                                              const float* __restrict__ bfs) {
    __shared__ __half mh[64];
    __shared__ float red[2];
    const int s = threadIdx.x, b = blockIdx.x;

    half2 wm[32], ws[32];
    #pragma unroll
    for (int j = 0; j < 32; j++) {
        wm[j] = __floats2half2_rn(Wfm[(2 * j) * 64 + s], Wfm[(2 * j + 1) * 64 + s]);
        ws[j] = __floats2half2_rn(Wfs[(2 * j) * 64 + s], Wfs[(2 * j + 1) * 64 + s]);
    }
    mh[s] = __float2half(im[b * 64 + s]);
    const float bmv = bfm[s], bsv = bfs[s];
    __syncthreads();

    const __half* pmp = g_pmh + (size_t)b * T_ * 64 + s;
    const float*  psp = g_ps  + (size_t)b * T_ * 64 + s;
    float pmv = __half2float(pmp[0]);
    float psv = psp[0];

    const half2 z2 = __float2half2_rn(0.f);
    float klsum = 0.f;
    for (int t = 0; t < T_; t++) {
        float npm = 0.f, nps = 1.f;
        if (t + 1 < T_) {
            npm = __half2float(pmp[(size_t)(t + 1) * 64]);
            nps = psp[(size_t)(t + 1) * 64];
        }
        const uint4* m4 = (const uint4*)mh;
        half2 am0 = z2, am1 = z2, as0 = z2, as1 = z2;
        {
            uint4 q0 = m4[0], q1 = m4[1], q2 = m4[2], q3 = m4[3];
            const half2* x0 = (const half2*)&q0; const half2* x1 = (const half2*)&q1;
            const half2* x2 = (const half2*)&q2; const half2* x3 = (const half2*)&q3;
            #pragma unroll
            for (int j = 0; j < 4; j++) {
                am0 = __hfma2(wm[j], x0[j], am0);      as0 = __hfma2(ws[j], x0[j], as0);
                am0 = __hfma2(wm[4 + j], x1[j], am0);  as0 = __hfma2(ws[4 + j], x1[j], as0);
                am0 = __hfma2(wm[8 + j], x2[j], am0);  as0 = __hfma2(ws[8 + j], x2[j], as0);
                am0 = __hfma2(wm[12 + j], x3[j], am0); as0 = __hfma2(ws[12 + j], x3[j], as0);
            }
        }
        {
            uint4 q4 = m4[4], q5 = m4[5], q6 = m4[6], q7 = m4[7];
            const half2* x4 = (const half2*)&q4; const half2* x5 = (const half2*)&q5;
            const half2* x6 = (const half2*)&q6; const half2* x7 = (const half2*)&q7;
            #pragma unroll
            for (int j = 0; j < 4; j++) {
                am1 = __hfma2(wm[16 + j], x4[j], am1); as1 = __hfma2(ws[16 + j], x4[j], as1);
                am1 = __hfma2(wm[20 + j], x5[j], am1); as1 = __hfma2(ws[20 + j], x5[j], as1);
                am1 = __hfma2(wm[24 + j], x6[j], am1); as1 = __hfma2(ws[24 + j], x6[j], as1);
                am1 = __hfma2(wm[28 + j], x7[j], am1); as1 = __hfma2(ws[28 + j], x7[j], as1);
            }
        }
        float2 vm = __half22float2(__hadd2(am0, am1));
        float2 vs = __half22float2(__hadd2(as0, as1));
        float amv = bmv + vm.x + vm.y;
        float asv = bsv + vs.x + vs.y;

        float sn = softplusf_(asv);
        float d  = pmv - amv;
        klsum += __logf(__fdividef(sn, psv))
               + __fdividef(psv * psv + d * d, 2.f * sn * sn) - 0.5f;
        __syncthreads();
        mh[s] = __float2half(amv);
        __syncthreads();
        pmv = npm; psv = nps;
    }
    #pragma unroll
    for (int off = 16; off; off >>= 1) klsum += __shfl_down_sync(0xffffffffu, klsum, off);
    if ((s & 31) == 0) red[s >> 5] = klsum;
    __syncthreads();
    if (s == 0) atomicAdd(&g_acc[0], (double)(red[0] + red[1]));
}

// ---------------------------------------------------------------------------
__global__ void k_fin(float* out) {
    out[0] = (float)(g_acc[0] / (double)BT_ - g_acc[1] / (double)B_);
}

// ---------------------------------------------------------------------------
extern "C" void kernel_launch(void* const* d_in, const int* in_sizes, int n_in,
                              void* d_out, int out_size) {
    const float* obs = (const float*)d_in[0];
    const float* im  = (const float*)d_in[1];
    // d_in[2] = initial_scale (unused by the reference computation)
    const float* Wfm = (const float*)d_in[3];
    const float* bfm = (const float*)d_in[4];
    const float* Wfs = (const float*)d_in[5];
    const float* bfs = (const float*)d_in[6];
    const float* Wgm = (const float*)d_in[7];
    const float* bgm = (const float*)d_in[8];
    const float* Wgs = (const float*)d_in[9];
    const float* bgs = (const float*)d_in[10];
    const float* K   = (const float*)d_in[11];
    const float* R   = (const float*)d_in[12];
    const float* bl  = (const float*)d_in[13];
    const float* Wrm = (const float*)d_in[14];
    const float* brm = (const float*)d_in[15];
    const float* Wrs = (const float*)d_in[16];
    const float* brs = (const float*)d_in[17];
    float* out = (float*)d_out;

    const int GEMM_SM = 2 * 128 * 136 * 2;          // 69632
    const int GEN_SM  = (128 * 72 + 256 * 72) * 2;  // 55296
    cudaFuncSetAttribute(k_xk,    cudaFuncAttributeMaxDynamicSharedMemorySize, GEMM_SM);
    cudaFuncSetAttribute(k_heads, cudaFuncAttributeMaxDynamicSharedMemorySize, GEMM_SM);
    cudaFuncSetAttribute(k_gen,   cudaFuncAttributeMaxDynamicSharedMemorySize, GEN_SM);

    k_zero<<<1, 32>>>();
    k_prep_w<<<128, 256>>>(K, R, Wrm, Wrs, Wgm, Wgs);
    k_xk<<<dim3(4, 1024), 256, GEMM_SM>>>(obs, bl);
    k_lstm<<<16, 512>>>();
    k_heads<<<1024, 256, GEMM_SM>>>(brm, brs);
    k_gen<<<1024, 512, GEN_SM>>>(obs, bgm, bgs);
    k_prior<<<256, 64>>>(im, Wfm, bfm, Wfs, bfs);
    k_fin<<<1, 1>>>(out);
}

// round 7
// speedup vs baseline: 1.3255x; 1.3255x over previous
#include <cuda_runtime.h>
#include <cuda_fp16.h>
#include <math.h>

#define B_  256
#define T_  512
#define S_  64
#define O_  128
#define H_  128
#define G4  512   // 4*H
#define BT_ ((size_t)B_ * T_)

// ---------------- scratch (device globals; no runtime allocation) ----------
__device__ __half g_gzh[BT_ * G4];         // 134 MB : obs@K + b (half)
__device__ __half g_hsh[BT_ * H_];         // 33.5 MB LSTM hidden (half)
__device__ __half g_pmh[BT_ * S_];         // 16.8 MB posterior mean (half)
__device__ float  g_ps [BT_ * S_];         // 33.5 MB posterior scale (fp32)
__device__ __half g_KTh [512 * 128];       // K^T  (n-major)
__device__ __half g_WrTh[128 * 128];       // [Wrm|Wrs]^T (n-major, n<64 mean)
__device__ __half g_WgTh[256 * 64];        // [Wgm|Wgs]^T (n-major, n<128 mean)
__device__ float  g_cp[7][65][65];         // Aug^(64j), j=1..7 (augmented [W|b;0|1])
__device__ double g_acc[2];                // [0]=KL sum, [1]=recon-logp sum

__device__ __forceinline__ float softplusf_(float x) {
    return fmaxf(x, 0.f) + __logf(1.f + __expf(-fabsf(x)));
}
__device__ __forceinline__ float tanha_(float x) {
    float y; asm("tanh.approx.f32 %0, %1;" : "=f"(y) : "f"(x)); return y;
}
__device__ __forceinline__ float sigt_(float x) {   // sigmoid via MUFU.TANH
    return fmaf(tanha_(0.5f * x), 0.5f, 0.5f);
}

__device__ __forceinline__ void mma16816(float* c, const unsigned* a, const unsigned* b) {
    asm volatile(
        "mma.sync.aligned.m16n8k16.row.col.f32.f16.f16.f32 "
        "{%0,%1,%2,%3}, {%4,%5,%6,%7}, {%8,%9}, {%0,%1,%2,%3};\n"
        : "+f"(c[0]), "+f"(c[1]), "+f"(c[2]), "+f"(c[3])
        : "r"(a[0]), "r"(a[1]), "r"(a[2]), "r"(a[3]), "r"(b[0]), "r"(b[1]));
}

// ---------------------------------------------------------------------------
__global__ void k_zero() { if (threadIdx.x < 2) g_acc[threadIdx.x] = 0.0; }

// weight transposes/concats -> half
__global__ void k_prep_w(const float* __restrict__ K,  const float* __restrict__ Wrm,
                         const float* __restrict__ Wrs, const float* __restrict__ Wgm,
                         const float* __restrict__ Wgs) {
    int stride = gridDim.x * blockDim.x;
    for (int i = blockIdx.x * blockDim.x + threadIdx.x; i < 98304; i += stride) {
        if (i < 65536) {
            int n = i >> 7, k = i & 127;
            g_KTh[i] = __float2half(K[k * 512 + n]);
        } else if (i < 81920) {
            int j = i - 65536; int n = j >> 7, k = j & 127;
            float v = (n < 64) ? Wrm[k * 64 + n] : Wrs[k * 64 + (n - 64)];
            g_WrTh[j] = __float2half(v);
        } else {
            int j = i - 81920; int n = j >> 6, k = j & 63;
            float v = (n < 128) ? Wgm[k * 128 + n] : Wgs[k * 128 + (n - 128)];
            g_WgTh[j] = __float2half(v);
        }
    }
}

// ---------------------------------------------------------------------------
// Aug = [[Wfm, 0],[bfm, 1]] (65x65, row-vector convention).
// Compute Aug^64 via 6 squarings, then Aug^(64j) j=1..7 -> g_cp[j-1].
#define PW_N  65
#define PW_LD 66
__global__ __launch_bounds__(256) void k_powers(const float* __restrict__ Wfm,
                                                const float* __restrict__ bfm) {
    __shared__ float A[PW_N * PW_LD];      // squaring buffer -> Aug^64
    __shared__ float Cur[PW_N * PW_LD];    // running product
    const int tid = threadIdx.x;

    for (int i = tid; i < PW_N * PW_N; i += 256) {
        int r = i / PW_N, s = i % PW_N;
        float v;
        if (r < 64 && s < 64)      v = Wfm[r * 64 + s];
        else if (r == 64 && s < 64) v = bfm[s];
        else                        v = (r == 64 && s == 64) ? 1.f : 0.f;
        A[r * PW_LD + s] = v;
    }
    __syncthreads();

    float regs[17];
    #pragma unroll 1
    for (int d = 0; d < 6; d++) {          // A <- A*A, 6x  => Aug^64
        int c = 0;
        for (int i = tid; i < PW_N * PW_N; i += 256, c++) {
            int r = i / PW_N, s = i % PW_N;
            float acc = 0.f;
            for (int k = 0; k < PW_N; k++) acc += A[r * PW_LD + k] * A[k * PW_LD + s];
            regs[c] = acc;
        }
        __syncthreads();
        c = 0;
        for (int i = tid; i < PW_N * PW_N; i += 256, c++)
            A[(i / PW_N) * PW_LD + i % PW_N] = regs[c];
        __syncthreads();
    }
    for (int i = tid; i < PW_N * PW_N; i += 256) {
        int r = i / PW_N, s = i % PW_N;
        float v = A[r * PW_LD + s];
        Cur[r * PW_LD + s] = v;
        g_cp[0][r][s] = v;
    }
    __syncthreads();
    #pragma unroll 1
    for (int j = 2; j <= 7; j++) {         // Cur <- Cur*A  => Aug^(64j)
        int c = 0;
        for (int i = tid; i < PW_N * PW_N; i += 256, c++) {
            int r = i / PW_N, s = i % PW_N;
            float acc = 0.f;
            for (int k = 0; k < PW_N; k++) acc += Cur[r * PW_LD + k] * A[k * PW_LD + s];
            regs[c] = acc;
        }
        __syncthreads();
        c = 0;
        for (int i = tid; i < PW_N * PW_N; i += 256, c++) {
            int r = i / PW_N, s = i % PW_N;
            Cur[r * PW_LD + s] = regs[c];
            g_cp[j - 1][r][s] = regs[c];
        }
        __syncthreads();
    }
}

// ---------------------------------------------------------------------------
// gz = obs @ K + b via HMMA, output half, smem-staged coalesced stores.
__global__ __launch_bounds__(256) void k_xk(const float* __restrict__ obs,
                                            const float* __restrict__ bl) {
    extern __shared__ __half sm[];
    __half* As = sm;                 // [128][136]
    __half* Bt = sm + 128 * 136;     // [128][136]  (K^T tile / later C staging)
    const int tid = threadIdx.x;
    const int bt0 = blockIdx.y * 128;
    const int c0  = blockIdx.x * 128;

    const float4* ap = (const float4*)(obs + (size_t)bt0 * 128);
    #pragma unroll
    for (int i = tid; i < 128 * 32; i += 256) {
        int r = i >> 5, c = i & 31;
        float4 v = ap[r * 32 + c];
        *(half2*)&As[r * 136 + c * 4]     = __floats2half2_rn(v.x, v.y);
        *(half2*)&As[r * 136 + c * 4 + 2] = __floats2half2_rn(v.z, v.w);
    }
    const uint4* bp = (const uint4*)(g_KTh + (size_t)c0 * 128);
    #pragma unroll
    for (int i = tid; i < 128 * 16; i += 256) {
        int r = i >> 4, c = i & 15;
        *(uint4*)&Bt[r * 136 + c * 8] = bp[r * 16 + c];
    }
    __syncthreads();

    const int w = tid >> 5, l = tid & 31, g = l >> 2, tg = l & 3;
    const int m0 = w * 16;
    float acc[16][4];
    #pragma unroll
    for (int i = 0; i < 16; i++)
        #pragma unroll
        for (int j = 0; j < 4; j++) acc[i][j] = 0.f;

    #pragma unroll
    for (int kk = 0; kk < 8; kk++) {
        const int kb = kk * 16 + tg * 2;
        unsigned a[4];
        a[0] = *(const unsigned*)&As[(m0 + g)     * 136 + kb];
        a[1] = *(const unsigned*)&As[(m0 + g + 8) * 136 + kb];
        a[2] = *(const unsigned*)&As[(m0 + g)     * 136 + kb + 8];
        a[3] = *(const unsigned*)&As[(m0 + g + 8) * 136 + kb + 8];
        #pragma unroll
        for (int na = 0; na < 16; na++) {
            unsigned b[2];
            b[0] = *(const unsigned*)&Bt[(na * 8 + g) * 136 + kb];
            b[1] = *(const unsigned*)&Bt[(na * 8 + g) * 136 + kb + 8];
            mma16816(acc[na], a, b);
        }
    }
    __syncthreads();                 // done reading Bt; reuse it as C staging
    #pragma unroll
    for (int na = 0; na < 16; na++) {
        int cc = na * 8 + tg * 2;
        float2 bb = *(const float2*)&bl[c0 + cc];
        *(half2*)&Bt[(m0 + g) * 136 + cc]     = __floats2half2_rn(acc[na][0] + bb.x,
                                                                  acc[na][1] + bb.y);
        *(half2*)&Bt[(m0 + g + 8) * 136 + cc] = __floats2half2_rn(acc[na][2] + bb.x,
                                                                  acc[na][3] + bb.y);
    }
    __syncthreads();
    #pragma unroll
    for (int i = tid; i < 128 * 16; i += 256) {
        int r = i >> 4, c = i & 15;
        uint4 v = *(uint4*)&Bt[r * 136 + c * 8];
        *(uint4*)&g_gzh[(size_t)(bt0 + r) * 512 + c0 + c * 8] = v;
    }
}

// ---------------------------------------------------------------------------
// LSTM recurrence: 128 blocks x 512 thr, 2 batch rows/block.
// Thread owns gate column tid for both rows; weights in half2 regs,
// h broadcast from smem, zbuf exchange, MUFU.TANH gates.
__global__ __launch_bounds__(512, 1) void k_lstm(const float* __restrict__ R) {
    __shared__ __half hh[2 * 128];
    __shared__ float  zbuf[2 * 512];
    const int tid = threadIdx.x;
    const int b0  = blockIdx.x * 2;

    half2 wreg[64];
    #pragma unroll
    for (int j = 0; j < 64; j++)
        wreg[j] = __floats2half2_rn(R[(size_t)(2 * j) * 512 + tid],
                                    R[(size_t)(2 * j + 1) * 512 + tid]);
    if (tid < 256) hh[tid] = __float2half(0.f);

    const __half* gz0 = g_gzh + (size_t)b0 * T_ * 512 + tid;
    const __half* gz1 = gz0 + (size_t)T_ * 512;
    const int r_ = tid >> 7, k_ = tid & 127;         // combine role (tid<256)
    __half* hout = g_hsh + (size_t)(b0 + r_) * T_ * 128 + k_;
    float cst = 0.f;

    float gv0 = __half2float(gz0[0]);
    float gv1 = __half2float(gz1[0]);
    __syncthreads();

    const half2 z2 = __float2half2_rn(0.f);
    for (int t = 0; t < T_; t++) {
        float ngv0 = 0.f, ngv1 = 0.f;
        if (t + 1 < T_) {
            ngv0 = __half2float(gz0[(size_t)(t + 1) * 512]);
            ngv1 = __half2float(gz1[(size_t)(t + 1) * 512]);
        }
        float fs0 = gv0, fs1 = gv1;
        #pragma unroll
        for (int r = 0; r < 2; r++) {
            const uint4* hq = (const uint4*)(hh + r * 128);
            half2 a0 = z2, a1 = z2, a2 = z2, a3 = z2;
            #pragma unroll
            for (int q = 0; q < 4; q++) {            // 4 uint4 per accumulator
                uint4 v0 = hq[q], v1 = hq[4 + q], v2 = hq[8 + q], v3 = hq[12 + q];
                const half2* x0 = (const half2*)&v0;
                const half2* x1 = (const half2*)&v1;
                const half2* x2 = (const half2*)&v2;
                const half2* x3 = (const half2*)&v3;
                #pragma unroll
                for (int j = 0; j < 4; j++) {
                    a0 = __hfma2(wreg[q * 4 + j],      x0[j], a0);
                    a1 = __hfma2(wreg[16 + q * 4 + j], x1[j], a1);
                    a2 = __hfma2(wreg[32 + q * 4 + j], x2[j], a2);
                    a3 = __hfma2(wreg[48 + q * 4 + j], x3[j], a3);
                }
            }
            half2 s2 = __hadd2(__hadd2(a0, a1), __hadd2(a2, a3));
            float2 v = __half22float2(s2);
            if (r == 0) fs0 += v.x + v.y; else fs1 += v.x + v.y;
        }
        zbuf[tid]       = fs0;
        zbuf[512 + tid] = fs1;
        __syncthreads();
        if (tid < 256) {
            const float* zb = zbuf + r_ * 512;
            float zi = zb[k_], zf = zb[128 + k_], zg = zb[256 + k_], zo = zb[384 + k_];
            cst = sigt_(zf) * cst + sigt_(zi) * tanha_(zg);
            float hv = sigt_(zo) * tanha_(cst);
            __half h16 = __float2half(hv);
            hh[r_ * 128 + k_] = h16;
            hout[(size_t)t * 128] = h16;
        }
        __syncthreads();
        gv0 = ngv0; gv1 = ngv1;
    }
}

// ---------------------------------------------------------------------------
// heads: [hs]@[Wrm|Wrs] via HMMA.  grid 1024, 256 thr.  tile 128x128, k=128.
__global__ __launch_bounds__(256) void k_heads(const float* __restrict__ brm,
                                               const float* __restrict__ brs) {
    extern __shared__ __half sm[];
    __half* As = sm;                 // [128][136]
    __half* Bt = sm + 128 * 136;     // [128][136]
    const int tid = threadIdx.x;
    const int bt0 = blockIdx.x * 128;

    const uint4* ap = (const uint4*)(g_hsh + (size_t)bt0 * 128);
    const uint4* bp = (const uint4*)g_WrTh;
    #pragma unroll
    for (int i = tid; i < 128 * 16; i += 256) {
        int r = i >> 4, c = i & 15;
        *(uint4*)&As[r * 136 + c * 8] = ap[r * 16 + c];
        *(uint4*)&Bt[r * 136 + c * 8] = bp[r * 16 + c];
    }
    __syncthreads();

    const int w = tid >> 5, l = tid & 31, g = l >> 2, tg = l & 3;
    const int m0 = w * 16;
    float acc[16][4];
    #pragma unroll
    for (int i = 0; i < 16; i++)
        #pragma unroll
        for (int j = 0; j < 4; j++) acc[i][j] = 0.f;

    #pragma unroll
    for (int kk = 0; kk < 8; kk++) {
        const int kb = kk * 16 + tg * 2;
        unsigned a[4];
        a[0] = *(const unsigned*)&As[(m0 + g)     * 136 + kb];
        a[1] = *(const unsigned*)&As[(m0 + g + 8) * 136 + kb];
        a[2] = *(const unsigned*)&As[(m0 + g)     * 136 + kb + 8];
        a[3] = *(const unsigned*)&As[(m0 + g + 8) * 136 + kb + 8];
        #pragma unroll
        for (int na = 0; na < 16; na++) {
            unsigned b[2];
            b[0] = *(const unsigned*)&Bt[(na * 8 + g) * 136 + kb];
            b[1] = *(const unsigned*)&Bt[(na * 8 + g) * 136 + kb + 8];
            mma16816(acc[na], a, b);
        }
    }
    #pragma unroll
    for (int na = 0; na < 16; na++) {
        int cc = na * 8 + tg * 2;                 // 0..127 within concat
        int r0 = bt0 + m0 + g, r1 = r0 + 8;
        if (cc < 64) {
            float2 bm = *(const float2*)&brm[cc];
            *(half2*)&g_pmh[(size_t)r0 * 64 + cc] =
                __floats2half2_rn(acc[na][0] + bm.x, acc[na][1] + bm.y);
            *(half2*)&g_pmh[(size_t)r1 * 64 + cc] =
                __floats2half2_rn(acc[na][2] + bm.x, acc[na][3] + bm.y);
        } else {
            int c2 = cc - 64;
            float2 bs = *(const float2*)&brs[c2];
            *(float2*)&g_ps[(size_t)r0 * 64 + c2] =
                make_float2(softplusf_(acc[na][0] + bs.x), softplusf_(acc[na][1] + bs.y));
            *(float2*)&g_ps[(size_t)r1 * 64 + c2] =
                make_float2(softplusf_(acc[na][2] + bs.x), softplusf_(acc[na][3] + bs.y));
        }
    }
}

// ---------------------------------------------------------------------------
// generator + recon term via HMMA, fused reduction.  grid 1024, 512 thr.
__global__ __launch_bounds__(512) void k_gen(const float* __restrict__ obs,
                                             const float* __restrict__ bgm,
                                             const float* __restrict__ bgs) {
    extern __shared__ __half sm[];
    __half* As = sm;                 // [128][72]
    __half* Bt = sm + 128 * 72;      // [256][72]
    __shared__ float red[16];
    const int tid = threadIdx.x;
    const int bt0 = blockIdx.x * 128;

    const uint4* ap = (const uint4*)(g_pmh + (size_t)bt0 * 64);
    #pragma unroll
    for (int i = tid; i < 128 * 8; i += 512) {
        int r = i >> 3, c = i & 7;
        *(uint4*)&As[r * 72 + c * 8] = ap[r * 8 + c];
    }
    const uint4* bp = (const uint4*)g_WgTh;
    #pragma unroll
    for (int i = tid; i < 256 * 8; i += 512) {
        int r = i >> 3, c = i & 7;
        *(uint4*)&Bt[r * 72 + c * 8] = bp[i];
    }
    __syncthreads();

    const int w = tid >> 5, l = tid & 31, g = l >> 2, tg = l & 3;
    const int strip = w >> 1, ch = w & 1;
    const int m0 = strip * 16;
    float am[8][4], as_[8][4];
    #pragma unroll
    for (int i = 0; i < 8; i++)
        #pragma unroll
        for (int j = 0; j < 4; j++) { am[i][j] = 0.f; as_[i][j] = 0.f; }

    #pragma unroll
    for (int kk = 0; kk < 4; kk++) {
        const int kb = kk * 16 + tg * 2;
        unsigned a[4];
        a[0] = *(const unsigned*)&As[(m0 + g)     * 72 + kb];
        a[1] = *(const unsigned*)&As[(m0 + g + 8) * 72 + kb];
        a[2] = *(const unsigned*)&As[(m0 + g)     * 72 + kb + 8];
        a[3] = *(const unsigned*)&As[(m0 + g + 8) * 72 + kb + 8];
        #pragma unroll
        for (int na = 0; na < 8; na++) {
            int nmu = ch * 64 + na * 8 + g;
            unsigned b[2], b2[2];
            b[0]  = *(const unsigned*)&Bt[nmu * 72 + kb];
            b[1]  = *(const unsigned*)&Bt[nmu * 72 + kb + 8];
            b2[0] = *(const unsigned*)&Bt[(nmu + 128) * 72 + kb];
            b2[1] = *(const unsigned*)&Bt[(nmu + 128) * 72 + kb + 8];
            mma16816(am[na], a, b);
            mma16816(as_[na], a, b2);
        }
    }

    float lsum = 0.f;
    #pragma unroll
    for (int na = 0; na < 8; na++) {
        int oc = ch * 64 + na * 8 + tg * 2;
        float2 bm2 = *(const float2*)&bgm[oc];
        float2 bs2 = *(const float2*)&bgs[oc];
        int r0 = bt0 + m0 + g, r1 = r0 + 8;
        float2 o0 = *(const float2*)&obs[(size_t)r0 * 128 + oc];
        float2 o1 = *(const float2*)&obs[(size_t)r1 * 128 + oc];
        float mu, sg, d;
        mu = am[na][0] + bm2.x; sg = softplusf_(as_[na][0] + bs2.x);
        d = __fdividef(o0.x - mu, sg); lsum += -0.5f * d * d - __logf(sg);
        mu = am[na][1] + bm2.y; sg = softplusf_(as_[na][1] + bs2.y);
        d = __fdividef(o0.y - mu, sg); lsum += -0.5f * d * d - __logf(sg);
        mu = am[na][2] + bm2.x; sg = softplusf_(as_[na][2] + bs2.x);
        d = __fdividef(o1.x - mu, sg); lsum += -0.5f * d * d - __logf(sg);
        mu = am[na][3] + bm2.y; sg = softplusf_(as_[na][3] + bs2.y);
        d = __fdividef(o1.y - mu, sg); lsum += -0.5f * d * d - __logf(sg);
    }
    lsum -= 32.f * 0.91893853320467274f;   // 32 elements x 0.5*log(2pi)

    #pragma unroll
    for (int off = 16; off; off >>= 1) lsum += __shfl_down_sync(0xffffffffu, lsum, off);
    if (l == 0) red[w] = lsum;
    __syncthreads();
    if (tid == 0) {
        float s = 0.f;
        #pragma unroll
        for (int i = 0; i < 16; i++) s += red[i];
        atomicAdd(&g_acc[1], (double)s);
    }
}

// ---------------------------------------------------------------------------
// Prior rollout + KL, chunk-parallel: block = (b, j) rolls t in [64j, 64j+64)
// from the closed-form checkpoint (m0,1)@Aug^(64j). 2048 blocks x 64 thr.
__global__ __launch_bounds__(64) void k_prior2(const float* __restrict__ im,
                                               const float* __restrict__ Wfm,
                                               const float* __restrict__ bfm,
                                               const float* __restrict__ Wfs,
                                               const float* __restrict__ bfs) {
    __shared__ float  m0s[64];
    __shared__ __half mh[2][80];      // ping-pong, 16B-aligned rows
    __shared__ float  red[2];
    const int s = threadIdx.x;
    const int b = blockIdx.x >> 3, j = blockIdx.x & 7;

    half2 wm[32], ws[32];
    #pragma unroll
    for (int q = 0; q < 32; q++) {
        wm[q] = __floats2half2_rn(Wfm[(2 * q) * 64 + s], Wfm[(2 * q + 1) * 64 + s]);
        ws[q] = __floats2half2_rn(Wfs[(2 * q) * 64 + s], Wfs[(2 * q + 1) * 64 + s]);
    }
    m0s[s] = im[b * 64 + s];
    const float bmv = bfm[s], bsv = bfs[s];
    __syncthreads();

    float mv;
    if (j == 0) {
        mv = m0s[s];
    } else {
        const float* CP = &g_cp[j - 1][0][0];     // [65][65]
        float acc = CP[64 * 65 + s];              // bias row
        #pragma unroll 16
        for (int k = 0; k < 64; k++) acc += m0s[k] * CP[k * 65 + s];
        mv = acc;
    }
    mh[0][s] = __float2half(mv);
    __syncthreads();

    const int t0 = j * 64;
    const __half* pmp = g_pmh + ((size_t)b * T_ + t0) * 64 + s;
    const float*  psp = g_ps  + ((size_t)b * T_ + t0) * 64 + s;
    float pmv = __half2float(pmp[0]);
    float psv = psp[0];

    const half2 z2 = __float2half2_rn(0.f);
    float klsum = 0.f;
    int pp = 0;
    for (int i = 0; i < 64; i++) {
        float npm = 0.f, nps = 1.f;
        if (i + 1 < 64) {
            npm = __half2float(pmp[(size_t)(i + 1) * 64]);
            nps = psp[(size_t)(i + 1) * 64];
        }
        const uint4* m4 = (const uint4*)mh[pp];
        half2 am0 = z2, am1 = z2, as0 = z2, as1 = z2;
        {
            uint4 q0 = m4[0], q1 = m4[1], q2 = m4[2], q3 = m4[3];
            const half2* x0 = (const half2*)&q0; const half2* x1 = (const half2*)&q1;
            const half2* x2 = (const half2*)&q2; const half2* x3 = (const half2*)&q3;
            #pragma unroll
            for (int q = 0; q < 4; q++) {
                am0 = __hfma2(wm[q], x0[q], am0);      as0 = __hfma2(ws[q], x0[q], as0);
                am0 = __hfma2(wm[4 + q], x1[q], am0);  as0 = __hfma2(ws[4 + q], x1[q], as0);
                am0 = __hfma2(wm[8 + q], x2[q], am0);  as0 = __hfma2(ws[8 + q], x2[q], as0);
                am0 = __hfma2(wm[12 + q], x3[q], am0); as0 = __hfma2(ws[12 + q], x3[q], as0);
            }
        }
        {
            uint4 q4 = m4[4], q5 = m4[5], q6 = m4[6], q7 = m4[7];
            const half2* x4 = (const half2*)&q4; const half2* x5 = (const half2*)&q5;
            const half2* x6 = (const half2*)&q6; const half2* x7 = (const half2*)&q7;
            #pragma unroll
            for (int q = 0; q < 4; q++) {
                am1 = __hfma2(wm[16 + q], x4[q], am1); as1 = __hfma2(ws[16 + q], x4[q], as1);
                am1 = __hfma2(wm[20 + q], x5[q], am1); as1 = __hfma2(ws[20 + q], x5[q], as1);
                am1 = __hfma2(wm[24 + q], x6[q], am1); as1 = __hfma2(ws[24 + q], x6[q], as1);
                am1 = __hfma2(wm[28 + q], x7[q], am1); as1 = __hfma2(ws[28 + q], x7[q], as1);
            }
        }
        float2 vm = __half22float2(__hadd2(am0, am1));
        float2 vs = __half22float2(__hadd2(as0, as1));
        float amv = bmv + vm.x + vm.y;
        float asv = bsv + vs.x + vs.y;

        float sn = softplusf_(asv);
        float d  = pmv - amv;
        klsum += __logf(__fdividef(sn, psv))
               + __fdividef(psv * psv + d * d, 2.f * sn * sn) - 0.5f;

        mh[pp ^ 1][s] = __float2half(amv);
        __syncthreads();
        pp ^= 1;
        pmv = npm; psv = nps;
    }
    #pragma unroll
    for (int off = 16; off; off >>= 1) klsum += __shfl_down_sync(0xffffffffu, klsum, off);
    if ((s & 31) == 0) red[s >> 5] = klsum;
    __syncthreads();
    if (s == 0) atomicAdd(&g_acc[0], (double)(red[0] + red[1]));
}

// ---------------------------------------------------------------------------
__global__ void k_fin(float* out) {
    out[0] = (float)(g_acc[0] / (double)BT_ - g_acc[1] / (double)B_);
}

// ---------------------------------------------------------------------------
extern "C" void kernel_launch(void* const* d_in, const int* in_sizes, int n_in,
                              void* d_out, int out_size) {
    const float* obs = (const float*)d_in[0];
    const float* im  = (const float*)d_in[1];
    // d_in[2] = initial_scale (unused by the reference computation)
    const float* Wfm = (const float*)d_in[3];
    const float* bfm = (const float*)d_in[4];
    const float* Wfs = (const float*)d_in[5];
    const float* bfs = (const float*)d_in[6];
    const float* Wgm = (const float*)d_in[7];
    const float* bgm = (const float*)d_in[8];
    const float* Wgs = (const float*)d_in[9];
    const float* bgs = (const float*)d_in[10];
    const float* K   = (const float*)d_in[11];
    const float* R   = (const float*)d_in[12];
    const float* bl  = (const float*)d_in[13];
    const float* Wrm = (const float*)d_in[14];
    const float* brm = (const float*)d_in[15];
    const float* Wrs = (const float*)d_in[16];
    const float* brs = (const float*)d_in[17];
    float* out = (float*)d_out;

    const int GEMM_SM = 2 * 128 * 136 * 2;          // 69632
    const int GEN_SM  = (128 * 72 + 256 * 72) * 2;  // 55296
    cudaFuncSetAttribute(k_xk,    cudaFuncAttributeMaxDynamicSharedMemorySize, GEMM_SM);
    cudaFuncSetAttribute(k_heads, cudaFuncAttributeMaxDynamicSharedMemorySize, GEMM_SM);
    cudaFuncSetAttribute(k_gen,   cudaFuncAttributeMaxDynamicSharedMemorySize, GEN_SM);

    k_zero<<<1, 32>>>();
    k_prep_w<<<128, 256>>>(K, Wrm, Wrs, Wgm, Wgs);
    k_powers<<<1, 256>>>(Wfm, bfm);
    k_xk<<<dim3(4, 1024), 256, GEMM_SM>>>(obs, bl);
    k_lstm<<<128, 512>>>(R);
    k_heads<<<1024, 256, GEMM_SM>>>(brm, brs);
    k_gen<<<1024, 512, GEN_SM>>>(obs, bgm, bgs);
    k_prior2<<<2048, 64>>>(im, Wfm, bfm, Wfs, bfs);
    k_fin<<<1, 1>>>(out);
}